// round 1
// baseline (speedup 1.0000x reference)
#include <cuda_runtime.h>

#define NB 2
#define NH 16
#define NT 8192
#define ND 64
#define NM 8
#define NP 32                       // ND/2
#define BHTD (NB*NH*NT*ND)          // 33554432
#define TOK 64
#define THREADS 128

// Scratch (allocation-free): normalized Householder vectors + cos/sin table
__device__ float  g_U[NH*NM*ND];    // 8192 floats
__device__ float2 g_cs[NT*NP];      // 2 MB

// ---------------- prep kernels ----------------

__global__ void prep_U(const float* __restrict__ V) {
    int row = blockIdx.x;           // 0 .. NH*NM-1
    int l   = threadIdx.x;          // 32 lanes
    float a = V[row*ND + l];
    float b = V[row*ND + 32 + l];
    float s = a*a + b*b;
    #pragma unroll
    for (int o = 16; o; o >>= 1) s += __shfl_xor_sync(0xffffffffu, s, o);
    float inv = rsqrtf(s + 1e-16f);     // EPS^2 = 1e-16
    g_U[row*ND + l]      = a*inv;
    g_U[row*ND + 32 + l] = b*inv;
}

__global__ void prep_cs(const float* __restrict__ pos, const float* __restrict__ freq) {
    int idx = blockIdx.x*blockDim.x + threadIdx.x;   // NT*NP threads
    int t = idx >> 5, p = idx & 31;
    float a = pos[t] * freq[p];
    g_cs[idx] = make_float2(cosf(a), sinf(a));
}

// ---------------- main kernel ----------------
// Block: 128 threads = one (b,h) x 64 tokens x {q,k}. Thread owns one 64-elem vector.
// smem: zbuf 128x17 float4 (pitch-17 -> conflict-free), U 128 float4, cs 64x33 float2.

extern __shared__ float smem_raw[];

__global__ __launch_bounds__(THREADS) void hh_rope(
    const float* __restrict__ q, const float* __restrict__ k, float* __restrict__ out)
{
    float4* zbuf  = (float4*)smem_raw;          // 2176 float4 = 34816 B
    float4* ubuf  = zbuf + 128*17;              // 128 float4  =  2048 B
    float2* csbuf = (float2*)(ubuf + 128);      // 2112 float2 = 16896 B

    const int tid = threadIdx.x;
    const int bx  = blockIdx.x;                 // token tile (NT/TOK = 128)
    const int by  = blockIdx.y;                 // b*NH + h   (32)
    const int h   = by & (NH-1);
    const long t0 = (long)bx * TOK;

    // U for this head: 512 floats = 128 float4 (one LDG.128 per thread)
    {
        const float4* gu = (const float4*)g_U + (size_t)h*(NM*ND/4);
        ubuf[tid] = gu[tid];
    }
    // cos/sin for this token tile: 2048 float2, pitch-33 rows in smem
    {
        const float2* gcs = g_cs + t0*NP;
        #pragma unroll
        for (int i = 0; i < 16; i++) {
            int idx = i*THREADS + tid;          // 0..2047
            int tl = idx >> 5, p = idx & 31;
            csbuf[tl*33 + p] = gcs[idx];
        }
    }
    // Stage q tile (vectors 0..63) and k tile (64..127), coalesced
    {
        const float4* qb = (const float4*)(q + ((size_t)by*NT + t0)*ND);
        const float4* kb = (const float4*)(k + ((size_t)by*NT + t0)*ND);
        #pragma unroll
        for (int i = 0; i < 8; i++) {
            int f = i*THREADS + tid;            // 0..1023
            int v = f >> 4, j4 = f & 15;
            zbuf[v*17 + j4] = qb[f];
        }
        #pragma unroll
        for (int i = 0; i < 8; i++) {
            int f = i*THREADS + tid;
            int v = f >> 4, j4 = f & 15;
            zbuf[(64 + v)*17 + j4] = kb[f];
        }
    }
    __syncthreads();

    // Pull this thread's vector into registers (conflict-free, pitch 17)
    float4 z[16];
    #pragma unroll
    for (int j = 0; j < 16; j++) z[j] = zbuf[tid*17 + j];

    // 8 Householder reflections, order m = M-1 .. 0 (matches reference)
    #pragma unroll 1
    for (int m = NM - 1; m >= 0; m--) {
        const float4* vv = ubuf + m*16;
        float ax = 0.f, ay = 0.f, az = 0.f, aw = 0.f;
        #pragma unroll
        for (int j = 0; j < 16; j++) {
            float4 v = vv[j];
            ax = fmaf(z[j].x, v.x, ax);
            ay = fmaf(z[j].y, v.y, ay);
            az = fmaf(z[j].z, v.z, az);
            aw = fmaf(z[j].w, v.w, aw);
        }
        float c = -2.0f * ((ax + ay) + (az + aw));
        #pragma unroll
        for (int j = 0; j < 16; j++) {
            float4 v = vv[j];
            z[j].x = fmaf(c, v.x, z[j].x);
            z[j].y = fmaf(c, v.y, z[j].y);
            z[j].z = fmaf(c, v.z, z[j].z);
            z[j].w = fmaf(c, v.w, z[j].w);
        }
    }

    // RoPE: pairs (2p, 2p+1)
    {
        const int tok = tid & 63;
        const float2* cs = csbuf + tok*33;
        #pragma unroll
        for (int j = 0; j < 16; j++) {
            float2 c0 = cs[2*j];
            float2 c1 = cs[2*j + 1];
            float xe = z[j].x, xo = z[j].y;
            z[j].x = fmaf(xe, c0.x, -xo*c0.y);
            z[j].y = fmaf(xe, c0.y,  xo*c0.x);
            xe = z[j].z; xo = z[j].w;
            z[j].z = fmaf(xe, c1.x, -xo*c1.y);
            z[j].w = fmaf(xe, c1.y,  xo*c1.x);
        }
    }

    // Write back to own smem row (no race: each thread owns its row), then coalesced store
    #pragma unroll
    for (int j = 0; j < 16; j++) zbuf[tid*17 + j] = z[j];
    __syncthreads();

    {
        float4* oq = (float4*)(out + ((size_t)by*NT + t0)*ND);
        float4* ok = (float4*)(out + (size_t)BHTD + ((size_t)by*NT + t0)*ND);
        #pragma unroll
        for (int i = 0; i < 8; i++) {
            int f = i*THREADS + tid;
            int v = f >> 4, j4 = f & 15;
            oq[f] = zbuf[v*17 + j4];
        }
        #pragma unroll
        for (int i = 0; i < 8; i++) {
            int f = i*THREADS + tid;
            int v = f >> 4, j4 = f & 15;
            ok[f] = zbuf[(64 + v)*17 + j4];
        }
    }
}

// ---------------- launch ----------------

extern "C" void kernel_launch(void* const* d_in, const int* in_sizes, int n_in,
                              void* d_out, int out_size) {
    const float* q    = (const float*)d_in[0];
    const float* k    = (const float*)d_in[1];
    const float* V    = (const float*)d_in[2];
    const float* pos  = (const float*)d_in[3];
    const float* freq = (const float*)d_in[4];
    float* out = (float*)d_out;

    const int smem_bytes = (128*17 + 128)*16 + 64*33*8;   // 53760
    cudaFuncSetAttribute(hh_rope, cudaFuncAttributeMaxDynamicSharedMemorySize, smem_bytes);

    prep_U<<<NH*NM, 32>>>(V);
    prep_cs<<<(NT*NP)/256, 256>>>(pos, freq);

    dim3 grid(NT/TOK, NB*NH);
    hh_rope<<<grid, THREADS, smem_bytes>>>(q, k, out);
}

// round 7
// speedup vs baseline: 1.0994x; 1.0994x over previous
#include <cuda_runtime.h>

#define NB 2
#define NH 16
#define NT 8192
#define ND 64
#define NM 8
#define NP 32                       // ND/2
#define BHTD (NB*NH*NT*ND)          // 33554432
#define TOK 64
#define THREADS 128
#define CS_BLOCKS 1024              // 1024*256 = NT*NP threads

typedef unsigned long long u64;

// Scratch (allocation-free): normalized Householder vectors + cos/sin table
__device__ float  g_U[NH*NM*ND];    // 8192 floats
__device__ float2 g_cs[NT*NP];      // 2 MB

// ---------------- packed f32x2 helpers ----------------
__device__ __forceinline__ u64 pack2(float lo, float hi) {
    u64 r; asm("mov.b64 %0, {%1,%2};" : "=l"(r) : "f"(lo), "f"(hi)); return r;
}
__device__ __forceinline__ void unpack2(u64 a, float& lo, float& hi) {
    asm("mov.b64 {%0,%1}, %2;" : "=f"(lo), "=f"(hi) : "l"(a));
}
__device__ __forceinline__ u64 ffma2(u64 a, u64 b, u64 c) {
    u64 d; asm("fma.rn.f32x2 %0, %1, %2, %3;" : "=l"(d) : "l"(a), "l"(b), "l"(c));
    return d;
}

// ---------------- fused prep kernel ----------------
// blocks [0, CS_BLOCKS): cos/sin table.  blocks [CS_BLOCKS, CS_BLOCKS+16): U rows.
__global__ void prep(const float* __restrict__ V, const float* __restrict__ pos,
                     const float* __restrict__ freq)
{
    int b = blockIdx.x;
    if (b < CS_BLOCKS) {
        int idx = b*256 + threadIdx.x;       // 0 .. NT*NP-1
        int t = idx >> 5, p = idx & 31;
        float a = pos[t] * freq[p];
        float s, c;
        sincosf(a, &s, &c);
        g_cs[idx] = make_float2(c, s);
    } else {
        int rb = b - CS_BLOCKS;              // 0..15
        int w = threadIdx.x >> 5, l = threadIdx.x & 31;
        int row = rb*8 + w;                  // 0..127 (= NH*NM-1)
        float a  = V[row*ND + l];
        float bb = V[row*ND + 32 + l];
        float s = a*a + bb*bb;
        #pragma unroll
        for (int o = 16; o; o >>= 1) s += __shfl_xor_sync(0xffffffffu, s, o);
        float inv = rsqrtf(s + 1e-16f);      // EPS^2
        g_U[row*ND + l]      = a*inv;
        g_U[row*ND + 32 + l] = bb*inv;
    }
}

// ---------------- main kernel ----------------
// Block: 128 threads = one (b,h) x 64 tokens x {q,k}. Thread owns one 64-elem vector,
// held as 32 packed f32x2 (even,odd) pairs in registers.
// smem: zbuf 128x17 float4 (pitch-17 -> conflict-free), U 128 float4, cs 64x33 float2.

extern __shared__ float smem_raw[];

__global__ __launch_bounds__(THREADS) void hh_rope(
    const float* __restrict__ q, const float* __restrict__ k, float* __restrict__ out)
{
    float4* zbuf  = (float4*)smem_raw;          // 2176 float4 = 34816 B
    float4* ubuf  = zbuf + 128*17;              // 128 float4  =  2048 B
    float2* csbuf = (float2*)(ubuf + 128);      // 2112 float2 = 16896 B

    const int tid = threadIdx.x;
    const int bx  = blockIdx.x;                 // token tile (NT/TOK = 128)
    const int by  = blockIdx.y;                 // b*NH + h   (32)
    const int h   = by & (NH-1);
    const long t0 = (long)bx * TOK;

    // U for this head: 512 floats = 128 float4
    {
        const float4* gu = (const float4*)g_U + (size_t)h*(NM*ND/4);
        ubuf[tid] = gu[tid];
    }
    // cos/sin for this token tile: 2048 float2, pitch-33 rows in smem
    {
        const float2* gcs = g_cs + t0*NP;
        #pragma unroll
        for (int i = 0; i < 16; i++) {
            int idx = i*THREADS + tid;          // 0..2047
            int tl = idx >> 5, p = idx & 31;
            csbuf[tl*33 + p] = gcs[idx];
        }
    }
    // Stage q tile (vectors 0..63) and k tile (64..127), coalesced
    {
        const float4* qb = (const float4*)(q + ((size_t)by*NT + t0)*ND);
        const float4* kb = (const float4*)(k + ((size_t)by*NT + t0)*ND);
        #pragma unroll
        for (int i = 0; i < 8; i++) {
            int f = i*THREADS + tid;            // 0..1023
            int v = f >> 4, j4 = f & 15;
            zbuf[v*17 + j4] = qb[f];
        }
        #pragma unroll
        for (int i = 0; i < 8; i++) {
            int f = i*THREADS + tid;
            int v = f >> 4, j4 = f & 15;
            zbuf[(64 + v)*17 + j4] = kb[f];
        }
    }
    __syncthreads();

    // Pull this thread's vector into packed registers (conflict-free, pitch 17)
    u64 zz[32];
    {
        const ulonglong2* zrow = (const ulonglong2*)(zbuf + tid*17);
        #pragma unroll
        for (int j = 0; j < 16; j++) {
            ulonglong2 t = zrow[j];
            zz[2*j]   = t.x;
            zz[2*j+1] = t.y;
        }
    }

    // 8 Householder reflections (m = M-1 .. 0), packed f32x2 math
    #pragma unroll 1
    for (int m = NM - 1; m >= 0; m--) {
        const ulonglong2* vv = (const ulonglong2*)(ubuf + m*16);
        u64 acc0 = 0ull, acc1 = 0ull;
        #pragma unroll
        for (int j = 0; j < 16; j++) {
            ulonglong2 v = vv[j];
            acc0 = ffma2(zz[2*j],   v.x, acc0);
            acc1 = ffma2(zz[2*j+1], v.y, acc1);
        }
        float a0, a1, a2, a3;
        unpack2(acc0, a0, a1);
        unpack2(acc1, a2, a3);
        float c = -2.0f * ((a0 + a1) + (a2 + a3));
        u64 cc = pack2(c, c);
        #pragma unroll
        for (int j = 0; j < 16; j++) {
            ulonglong2 v = vv[j];
            zz[2*j]   = ffma2(cc, v.x, zz[2*j]);
            zz[2*j+1] = ffma2(cc, v.y, zz[2*j+1]);
        }
    }

    // RoPE: zz[p] holds pair (even=xe, odd=xo) for frequency p
    {
        const int tok = tid & 63;
        const float2* cs = csbuf + tok*33;
        #pragma unroll
        for (int p = 0; p < 32; p++) {
            float2 c = cs[p];
            float xe, xo;
            unpack2(zz[p], xe, xo);
            float re = fmaf(xe, c.x, -(xo*c.y));
            float ro = fmaf(xe, c.y,   xo*c.x);
            zz[p] = pack2(re, ro);
        }
    }

    // Write back to own smem row, then coalesced store
    {
        ulonglong2* zrow = (ulonglong2*)(zbuf + tid*17);
        #pragma unroll
        for (int j = 0; j < 16; j++)
            zrow[j] = make_ulonglong2(zz[2*j], zz[2*j+1]);
    }
    __syncthreads();

    {
        float4* oq = (float4*)(out + ((size_t)by*NT + t0)*ND);
        float4* ok = (float4*)(out + (size_t)BHTD + ((size_t)by*NT + t0)*ND);
        #pragma unroll
        for (int i = 0; i < 8; i++) {
            int f = i*THREADS + tid;
            int v = f >> 4, j4 = f & 15;
            oq[f] = zbuf[v*17 + j4];
        }
        #pragma unroll
        for (int i = 0; i < 8; i++) {
            int f = i*THREADS + tid;
            int v = f >> 4, j4 = f & 15;
            ok[f] = zbuf[(64 + v)*17 + j4];
        }
    }
}

// ---------------- launch ----------------

extern "C" void kernel_launch(void* const* d_in, const int* in_sizes, int n_in,
                              void* d_out, int out_size) {
    const float* q    = (const float*)d_in[0];
    const float* k    = (const float*)d_in[1];
    const float* V    = (const float*)d_in[2];
    const float* pos  = (const float*)d_in[3];
    const float* freq = (const float*)d_in[4];
    float* out = (float*)d_out;

    const int smem_bytes = (128*17 + 128)*16 + 64*33*8;   // 53760
    cudaFuncSetAttribute(hh_rope, cudaFuncAttributeMaxDynamicSharedMemorySize, smem_bytes);

    prep<<<CS_BLOCKS + 16, 256>>>(V, pos, freq);

    dim3 grid(NT/TOK, NB*NH);
    hh_rope<<<grid, THREADS, smem_bytes>>>(q, k, out);
}